// round 11
// baseline (speedup 1.0000x reference)
#include <cuda_runtime.h>
#include <cuda_fp16.h>
#include <cstdint>

#define VNUM   100000
#define KNZ    8
#define BASE   64
#define DIM    9
#define BATCH  16
#define TV     128
#define THREADS 512
#define NCOL   (BATCH * DIM)     // 144
#define NELEM  (TV * DIM)        // 1152
#define SLAB   (BASE * DIM)      // 576
#define NTILES ((VNUM + TV - 1) / TV)   // 782
#define GRID   296               // 148 SMs x 2 resident blocks: persistent

#define ASTR   72                // A row stride, halves (144 B)
#define BSTR   72                // B row stride, halves (144 B)
#define SSTR   1156              // stage per-batch stride, floats (conflict-free STS)

// smem map:
//   OFF_B     =     0 : B fp16 [144][72] = 20736 B   (persists across tiles)
//   OFF_A     = 20736 : A fp16 [128][72] = 18432 B   (ends 39168)
//   OFF_FS    = 39168 : base_fs f32 scratch 36864 B  (init only; ends 76032)
//   OFF_STAGE = 20736 : stage f32 [16][1156] = 73984 B (aliases A+FS; ends 94720)
#define OFF_B     0
#define OFF_A     20736
#define OFF_FS    39168
#define OFF_STAGE 20736
#define SMEM_TOTAL 94720

static __device__ __forceinline__ void mma16816(float c[4],
                                                const uint32_t a[4],
                                                uint32_t b0, uint32_t b1) {
    asm volatile(
        "mma.sync.aligned.m16n8k16.row.col.f32.f16.f16.f32 "
        "{%0,%1,%2,%3}, {%4,%5,%6,%7}, {%8,%9}, {%0,%1,%2,%3};"
        : "+f"(c[0]), "+f"(c[1]), "+f"(c[2]), "+f"(c[3])
        : "r"(a[0]), "r"(a[1]), "r"(a[2]), "r"(a[3]), "r"(b0), "r"(b1));
}

__global__ __launch_bounds__(THREADS, 2)
void skin_persist_kernel(const float* __restrict__ base_fs,
                         const float* __restrict__ ws,
                         const void*  __restrict__ vb_raw,
                         float* __restrict__ out) {
    extern __shared__ char smem[];
    const int tid = threadIdx.x;
    const int wid = tid >> 5;
    const int lid = tid & 31;
    const int g   = lid >> 2;       // mma group (0..7)
    const int tg  = lid & 3;        // thread-in-group (0..3)

    // ---- dtype self-detect (register-resident across the whole loop) ----
    // odd int32 slots of the first 64 int64-candidates (first 512 B, in-bounds
    // under either dtype). int64 data in [0,64) => all odd slots zero.
    const int* vb32 = (const int*)vb_raw;
    const int bad = (vb32[2 * lid + 1] != 0) | (vb32[2 * (lid + 32) + 1] != 0);
    const int is64 = (__ballot_sync(0xFFFFFFFFu, bad) == 0);

    // ---- init: stage base_fs into smem scratch (coalesced, 2304 float4) ----
    {
        const float4* src = (const float4*)base_fs;
        float4* dst = (float4*)(smem + OFF_FS);
        #pragma unroll
        for (int it = 0; it < 5; it++) {
            const int i = tid + it * THREADS;
            if (i < (BATCH * SLAB) / 4) dst[i] = src[i];
        }
    }
    __syncthreads();

    const int bid = blockIdx.x;
    for (int tile = bid; tile < NTILES; tile += GRID) {
        const int v0 = tile * TV;

        // ===== Phase A: softmax/A (warps 0..3) | B-build on FIRST tile (4..15) =====
        if (wid < 4) {
            const int v = v0 + tid;
            // zero own A row (9 float4; exclusive, conflict-free)
            float4* Arow4 = (float4*)((char*)smem + OFF_A + tid * (ASTR * 2));
            const float4 z = make_float4(0.f, 0.f, 0.f, 0.f);
            #pragma unroll
            for (int q = 0; q < 9; q++) Arow4[q] = z;

            if (v < VNUM) {
                const float4* wp = reinterpret_cast<const float4*>(ws + (size_t)v * KNZ);
                float4 a4 = wp[0], b4 = wp[1];
                float x[8] = {a4.x, a4.y, a4.z, a4.w, b4.x, b4.y, b4.z, b4.w};
                float m = x[0];
                #pragma unroll
                for (int j = 1; j < 8; j++) m = fmaxf(m, x[j]);
                float s = 0.f;
                #pragma unroll
                for (int j = 0; j < 8; j++) { x[j] = __expf(x[j] - m); s += x[j]; }
                const float inv = 1.f / s;

                int idx[8];
                if (is64) {
                    const longlong2* ip = reinterpret_cast<const longlong2*>(
                        (const char*)vb_raw + (size_t)v * KNZ * 8);
                    #pragma unroll
                    for (int j = 0; j < 4; j++) {
                        longlong2 ii = ip[j];
                        idx[2 * j] = (int)ii.x; idx[2 * j + 1] = (int)ii.y;
                    }
                } else {
                    const int4* ip = reinterpret_cast<const int4*>(
                        (const char*)vb_raw + (size_t)v * KNZ * 4);
                    int4 i0 = ip[0], i1 = ip[1];
                    idx[0] = i0.x; idx[1] = i0.y; idx[2] = i0.z; idx[3] = i0.w;
                    idx[4] = i1.x; idx[5] = i1.y; idx[6] = i1.z; idx[7] = i1.w;
                }
                // vb sampled with replacement: merge duplicates in fp32, round once
                __half* Ah = (__half*)((char*)smem + OFF_A) + tid * ASTR;
                #pragma unroll
                for (int j = 0; j < 8; j++) {
                    bool first = true;
                    #pragma unroll
                    for (int i = 0; i < 8; i++)
                        if (i < j && idx[i] == idx[j]) first = false;
                    if (first) {
                        float acc = 0.f;
                        #pragma unroll
                        for (int i = 0; i < 8; i++)
                            if (i >= j && idx[i] == idx[j]) acc += x[i];
                        Ah[idx[j]] = __float2half_rn(acc * inv);
                    }
                }
            }
        } else if (tile == bid) {
            // B[n = d*16+b][k] fp16 from smem f32 (LDS stride 18 -> <=2-way);
            // STS.32 of half2 to 32 consecutive words (conflict-free). Once per block.
            const float* fs_s = (const float*)(smem + OFF_FS);
            __half2* B2 = (__half2*)((char*)smem + OFF_B);
            const int t = tid - 128;                   // 0..383
            #pragma unroll
            for (int it = 0; it < 12; it++) {          // 12*384 = 4608 half2
                const int j  = t + it * 384;
                const int n  = j >> 5;                 // row 0..143 (warp-uniform)
                const int kp = j & 31;                 // k-pair (lane)
                const int b  = n & 15;
                const int d  = n >> 4;
                const float f0 = fs_s[b * SLAB + kp * 18 + d];
                const float f1 = fs_s[b * SLAB + kp * 18 + 9 + d];
                B2[n * (BSTR / 2) + kp] = __floats2half2_rn(f0, f1);
            }
        }
        __syncthreads();

        // ===== Phase B: 16 warps; warp = (row-pair, col-half): 16r x 72c =====
        const int Rrow = (wid >> 1) * 16;    // 0..112
        const int hcol = wid & 1;            // n-tiles [9h, 9h+9)

        float acc[9][4];
        #pragma unroll
        for (int t = 0; t < 9; t++)
            #pragma unroll
            for (int q = 0; q < 4; q++) acc[t][q] = 0.f;

        {
            const char* Abase = smem + OFF_A + (Rrow + g) * (ASTR * 2) + 4 * tg;
            const char* Bbase = smem + OFF_B + (hcol * 9 * 8 + g) * (BSTR * 2) + 4 * tg;
            #pragma unroll
            for (int ks = 0; ks < 4; ks++) {           // ks-outer: only 4 A regs live
                uint32_t afr[4];
                afr[0] = *(const uint32_t*)(Abase + ks * 32);
                afr[1] = *(const uint32_t*)(Abase + ks * 32 + 8 * ASTR * 2);
                afr[2] = *(const uint32_t*)(Abase + ks * 32 + 16);
                afr[3] = *(const uint32_t*)(Abase + ks * 32 + 8 * ASTR * 2 + 16);
                #pragma unroll
                for (int t = 0; t < 9; t++) {
                    const char* Bt = Bbase + t * 8 * (BSTR * 2);
                    const uint32_t b0 = *(const uint32_t*)(Bt + ks * 32);
                    const uint32_t b1 = *(const uint32_t*)(Bt + ks * 32 + 16);
                    mma16816(acc[t], afr, b0, b1);
                }
            }
        }
        __syncthreads();   // A reads done before stage aliases A

        // ===== Phase C: C frags -> stage[b][row*9+d]; n = d*16+b => b=n&15, d=n>>4 =====
        float* stage = (float*)(smem + OFF_STAGE);
        {
            const int r0 = Rrow + g;
            #pragma unroll
            for (int t = 0; t < 9; t++) {
                const int n0 = (hcol * 9 + t) * 8 + 2 * tg;
                const int b0i = n0 & 15, d0 = n0 >> 4;
                const int n1 = n0 + 1;
                const int b1i = n1 & 15, d1 = n1 >> 4;
                stage[b0i * SSTR + r0 * DIM + d0]       = acc[t][0];
                stage[b1i * SSTR + r0 * DIM + d1]       = acc[t][1];
                stage[b0i * SSTR + (r0 + 8) * DIM + d0] = acc[t][2];
                stage[b1i * SSTR + (r0 + 8) * DIM + d1] = acc[t][3];
            }
        }
        __syncthreads();

        // ===== Phase D: coalesced copy-out (288 float4 per batch plane) =====
        const int nvalid4 = (min(NELEM, (VNUM - v0) * DIM)) >> 2;
        const float4* st4 = (const float4*)stage;
        #pragma unroll
        for (int it = 0; it < 9; it++) {               // 4608 float4
            const int f  = tid + it * THREADS;
            const int b  = f / (NELEM / 4);
            const int e4 = f - b * (NELEM / 4);
            if (e4 < nvalid4)
                *(float4*)(out + (size_t)b * ((size_t)VNUM * DIM) +
                           (size_t)v0 * DIM + e4 * 4) = st4[b * (SSTR / 4) + e4];
        }
        __syncthreads();   // stage fully read before next tile's A overwrites it
    }
}

extern "C" void kernel_launch(void* const* d_in, const int* in_sizes, int n_in,
                              void* d_out, int out_size) {
    const float* base_fs = (const float*)d_in[0];   // [16, 576] f32
    const float* ws      = (const float*)d_in[1];   // [800000] f32
    const void*  vb      = d_in[2];                 // [800000] i64 or i32 (detected inline)
    // d_in[3] = vv_index: statically repeat(arange(VNUM), 8); unused.
    float* out = (float*)d_out;                     // [16, 100000, 9] f32

    static bool attr_set = false;
    if (!attr_set) {
        cudaFuncSetAttribute(skin_persist_kernel,
                             cudaFuncAttributeMaxDynamicSharedMemorySize, SMEM_TOTAL);
        attr_set = true;
    }

    skin_persist_kernel<<<GRID, THREADS, SMEM_TOTAL>>>(base_fs, ws, vb, out);
}

// round 13
// speedup vs baseline: 1.1015x; 1.1015x over previous
#include <cuda_runtime.h>
#include <cuda_fp16.h>
#include <cstdint>

#define VNUM   100000
#define KNZ    8
#define BASE   64
#define DIM    9
#define BATCH  16
#define TV     128
#define THREADS 512
#define NCOL   (BATCH * DIM)     // 144
#define NELEM  (TV * DIM)        // 1152
#define SLAB   (BASE * DIM)      // 576

#define ASTR   72                // A row stride, halves (144 B)
#define BSTR   72                // B row stride, halves (144 B)
#define SSTR   1156              // stage per-batch stride, floats (conflict-free STS)

// smem map:
//   OFF_B  =     0 : B fp16 [144][72] = 20736 B   (row n = d*16 + b)
//   OFF_A  = 20736 : A fp16 [128][72] = 18432 B   (ends 39168)
//   OFF_FS = 39168 : base_fs f32 scratch 36864 B  (dead after B-build)
//   stage f32 [16][1156] = 73984 B aliases from 0 after the mma phase.
#define OFF_B     0
#define OFF_A     20736
#define OFF_FS    39168
#define SMEM_TOTAL 76032

static __device__ __forceinline__ void mma16816(float c[4],
                                                const uint32_t a[4],
                                                uint32_t b0, uint32_t b1) {
    asm volatile(
        "mma.sync.aligned.m16n8k16.row.col.f32.f16.f16.f32 "
        "{%0,%1,%2,%3}, {%4,%5,%6,%7}, {%8,%9}, {%0,%1,%2,%3};"
        : "+f"(c[0]), "+f"(c[1]), "+f"(c[2]), "+f"(c[3])
        : "r"(a[0]), "r"(a[1]), "r"(a[2]), "r"(a[3]), "r"(b0), "r"(b1));
}

__global__ __launch_bounds__(THREADS, 2)
void skin_fused_kernel(const float* __restrict__ base_fs,
                       const float* __restrict__ ws,
                       const void*  __restrict__ vb_raw,
                       float* __restrict__ out) {
    extern __shared__ char smem[];
    const int tid = threadIdx.x;
    const int wid = tid >> 5;
    const int lid = tid & 31;
    const int g   = lid >> 2;       // mma group (0..7)
    const int tg  = lid & 3;        // thread-in-group (0..3)
    const int v0  = blockIdx.x * TV;

    // ================= Phase A: role-split, no shared barrier =================
    if (wid < 4) {
        // --- warps 0..3: detect -> prefetch -> softmax -> exclusive A-row ---
        // dtype detect: odd int32 slots of first 64 int64-candidates (512 B,
        // in-bounds under either dtype). int64 data in [0,64) => all zero.
        const int* vb32 = (const int*)vb_raw;
        const int bad = (vb32[2 * lid + 1] != 0) | (vb32[2 * (lid + 32) + 1] != 0);
        const int is64 = (__ballot_sync(0xFFFFFFFFu, bad) == 0);

        const int v = v0 + tid;
        const bool valid = (v < VNUM);

        // issue long-latency loads FIRST (overlap with A zeroing below)
        float4 a4, b4;
        int idx[8];
        if (valid) {
            const float4* wp = reinterpret_cast<const float4*>(ws + (size_t)v * KNZ);
            a4 = wp[0]; b4 = wp[1];
            if (is64) {
                const longlong2* ip = reinterpret_cast<const longlong2*>(
                    (const char*)vb_raw + (size_t)v * KNZ * 8);
                longlong2 i0 = ip[0], i1 = ip[1], i2 = ip[2], i3 = ip[3];
                idx[0] = (int)i0.x; idx[1] = (int)i0.y;
                idx[2] = (int)i1.x; idx[3] = (int)i1.y;
                idx[4] = (int)i2.x; idx[5] = (int)i2.y;
                idx[6] = (int)i3.x; idx[7] = (int)i3.y;
            } else {
                const int4* ip = reinterpret_cast<const int4*>(
                    (const char*)vb_raw + (size_t)v * KNZ * 4);
                int4 i0 = ip[0], i1 = ip[1];
                idx[0] = i0.x; idx[1] = i0.y; idx[2] = i0.z; idx[3] = i0.w;
                idx[4] = i1.x; idx[5] = i1.y; idx[6] = i1.z; idx[7] = i1.w;
            }
        }

        // zero own A row while loads are in flight (exclusive, conflict-free)
        float4* Arow4 = (float4*)((char*)smem + OFF_A + tid * (ASTR * 2));
        const float4 z = make_float4(0.f, 0.f, 0.f, 0.f);
        #pragma unroll
        for (int q = 0; q < 9; q++) Arow4[q] = z;

        if (valid) {
            float x[8] = {a4.x, a4.y, a4.z, a4.w, b4.x, b4.y, b4.z, b4.w};
            float m = x[0];
            #pragma unroll
            for (int j = 1; j < 8; j++) m = fmaxf(m, x[j]);
            float s = 0.f;
            #pragma unroll
            for (int j = 0; j < 8; j++) { x[j] = __expf(x[j] - m); s += x[j]; }
            const float inv = 1.f / s;

            // vb sampled with replacement: merge duplicates in fp32, round once
            __half* Ah = (__half*)((char*)smem + OFF_A) + tid * ASTR;
            #pragma unroll
            for (int j = 0; j < 8; j++) {
                bool first = true;
                #pragma unroll
                for (int i = 0; i < 8; i++)
                    if (i < j && idx[i] == idx[j]) first = false;
                if (first) {
                    float acc = 0.f;
                    #pragma unroll
                    for (int i = 0; i < 8; i++)
                        if (i >= j && idx[i] == idx[j]) acc += x[i];
                    Ah[idx[j]] = __float2half_rn(acc * inv);
                }
            }
        }
    } else {
        // --- warps 4..15: stage FS (coalesced) -> named barrier -> build B ---
        const int t = tid - 128;                   // 0..383
        {
            const float4* src = (const float4*)base_fs;
            float4* dst = (float4*)(smem + OFF_FS);
            #pragma unroll
            for (int it = 0; it < 6; it++) {       // 6*384 = 2304 float4
                const int i = t + it * 384;
                if (i < (BATCH * SLAB) / 4) dst[i] = src[i];
            }
        }
        asm volatile("bar.sync 1, 384;" ::: "memory");   // warps 4..15 only

        // B[n = d*16+b][k] fp16 from smem f32 (LDS stride 18 -> <=2-way);
        // STS.32 of half2 to 32 consecutive words (conflict-free).
        const float* fs_s = (const float*)(smem + OFF_FS);
        __half2* B2 = (__half2*)((char*)smem + OFF_B);
        #pragma unroll
        for (int it = 0; it < 12; it++) {          // 12*384 = 4608 half2
            const int j  = t + it * 384;
            const int n  = j >> 5;                 // row 0..143 (warp-uniform)
            const int kp = j & 31;                 // k-pair (lane)
            const int b  = n & 15;
            const int d  = n >> 4;
            const float f0 = fs_s[b * SLAB + kp * 18 + d];
            const float f1 = fs_s[b * SLAB + kp * 18 + 9 + d];
            B2[n * (BSTR / 2) + kp] = __floats2half2_rn(f0, f1);
        }
    }
    __syncthreads();

    // ========== Phase B: 16 warps; warp = (row-pair, col-half): 16r x 72c ==========
    const int Rrow = (wid >> 1) * 16;    // 0..112
    const int hcol = wid & 1;            // n-tiles [9h, 9h+9)

    float acc[9][4];
    #pragma unroll
    for (int t = 0; t < 9; t++)
        #pragma unroll
        for (int q = 0; q < 4; q++) acc[t][q] = 0.f;

    {
        const char* Abase = smem + OFF_A + (Rrow + g) * (ASTR * 2) + 4 * tg;
        const char* Bbase = smem + OFF_B + (hcol * 9 * 8 + g) * (BSTR * 2) + 4 * tg;
        #pragma unroll
        for (int ks = 0; ks < 4; ks++) {           // ks-outer: only 4 A regs live
            uint32_t afr[4];
            afr[0] = *(const uint32_t*)(Abase + ks * 32);
            afr[1] = *(const uint32_t*)(Abase + ks * 32 + 8 * ASTR * 2);
            afr[2] = *(const uint32_t*)(Abase + ks * 32 + 16);
            afr[3] = *(const uint32_t*)(Abase + ks * 32 + 8 * ASTR * 2 + 16);
            #pragma unroll
            for (int t = 0; t < 9; t++) {
                const char* Bt = Bbase + t * 8 * (BSTR * 2);
                const uint32_t b0 = *(const uint32_t*)(Bt + ks * 32);
                const uint32_t b1 = *(const uint32_t*)(Bt + ks * 32 + 16);
                mma16816(acc[t], afr, b0, b1);
            }
        }
    }
    __syncthreads();   // all A/B reads done before stage aliases them

    // ==== Phase C: C frags -> stage[b][row*9+d]; col n = d*16+b => b=n&15, d=n>>4 ====
    float* stage = (float*)smem;
    {
        const int r0 = Rrow + g;
        #pragma unroll
        for (int t = 0; t < 9; t++) {
            const int n0 = (hcol * 9 + t) * 8 + 2 * tg;
            const int b0i = n0 & 15, d0 = n0 >> 4;
            const int n1 = n0 + 1;
            const int b1i = n1 & 15, d1 = n1 >> 4;
            stage[b0i * SSTR + r0 * DIM + d0]       = acc[t][0];
            stage[b1i * SSTR + r0 * DIM + d1]       = acc[t][1];
            stage[b0i * SSTR + (r0 + 8) * DIM + d0] = acc[t][2];
            stage[b1i * SSTR + (r0 + 8) * DIM + d1] = acc[t][3];
        }
    }
    __syncthreads();

    // ============ Phase D: coalesced copy-out (288 float4 per batch plane) ============
    const int nvalid4 = (min(NELEM, (VNUM - v0) * DIM)) >> 2;
    const float4* st4 = (const float4*)stage;
    #pragma unroll
    for (int it = 0; it < 9; it++) {               // 4608 float4
        const int f  = tid + it * THREADS;
        const int b  = f / (NELEM / 4);
        const int e4 = f - b * (NELEM / 4);
        if (e4 < nvalid4)
            *(float4*)(out + (size_t)b * ((size_t)VNUM * DIM) + (size_t)v0 * DIM + e4 * 4) =
                st4[b * (SSTR / 4) + e4];
    }
}

extern "C" void kernel_launch(void* const* d_in, const int* in_sizes, int n_in,
                              void* d_out, int out_size) {
    const float* base_fs = (const float*)d_in[0];   // [16, 576] f32
    const float* ws      = (const float*)d_in[1];   // [800000] f32
    const void*  vb      = d_in[2];                 // [800000] i64 or i32 (detected inline)
    // d_in[3] = vv_index: statically repeat(arange(VNUM), 8); unused.
    float* out = (float*)d_out;                     // [16, 100000, 9] f32

    static bool attr_set = false;
    if (!attr_set) {
        cudaFuncSetAttribute(skin_fused_kernel,
                             cudaFuncAttributeMaxDynamicSharedMemorySize, SMEM_TOTAL);
        attr_set = true;
    }

    const int blocks = (VNUM + TV - 1) / TV;        // 782
    skin_fused_kernel<<<blocks, THREADS, SMEM_TOTAL>>>(base_fs, ws, vb, out);
}